// round 8
// baseline (speedup 1.0000x reference)
#include <cuda_runtime.h>
#include <cuda_fp16.h>
#include <cstdint>
#include <math.h>

#define N_ 4096
#define F_ 512
#define TM 128
#define TNJ 128
#define BK 64
#define NCH (F_ / BK)            // 8 k-chunks
#define TILE_BYTES 16384         // 128 rows x 128B
#define STAGE_BYTES (2 * TILE_BYTES)   // Bh tile + Ah tile = 32KB
#define SMEM_TOTAL (3 * STAGE_BYTES)   // 98304, 2 CTAs/SM
#define PMAX 512                 // max positives per row (mean 256, max ~305)

// ---------------- scratch ----------------
__device__ __align__(16) __half g_ah[(size_t)N_ * F_];
__device__ __align__(16) __half g_bh[(size_t)N_ * F_];
__device__ float2 g_pos[(size_t)N_ * PMAX];   // (D, j-bits) per positive pair
__device__ int   g_poscnt[N_];
__device__ float g_negsum[N_];
__device__ float g_a2[N_], g_b2[N_];
__device__ int   g_cnt[16];
__device__ double g_sum;
__device__ int   g_done;

// ---------------- helpers ----------------
__device__ __forceinline__ uint32_t smem_u32(const void* p) {
    uint32_t r;
    asm("{ .reg .u64 t; cvta.to.shared.u64 t, %1; cvt.u32.u64 %0, t; }" : "=r"(r) : "l"(p));
    return r;
}
__device__ __forceinline__ float fsqrt_ap(float x) {
    float r; asm("sqrt.approx.f32 %0, %1;" : "=f"(r) : "f"(x)); return r;
}

#define LDSM4(r, addr) \
    asm volatile("ldmatrix.sync.aligned.m8n8.x4.shared.b16 {%0,%1,%2,%3}, [%4];" \
                 : "=r"((r)[0]), "=r"((r)[1]), "=r"((r)[2]), "=r"((r)[3]) : "r"(addr))

#define MMA16816(d, a, b0, b1) \
    asm volatile("mma.sync.aligned.m16n8k16.row.col.f32.f16.f16.f32 " \
                 "{%0,%1,%2,%3}, {%4,%5,%6,%7}, {%8,%9}, {%0,%1,%2,%3};" \
                 : "+f"((d)[0]), "+f"((d)[1]), "+f"((d)[2]), "+f"((d)[3]) \
                 : "r"((a)[0]), "r"((a)[1]), "r"((a)[2]), "r"((a)[3]), "r"(b0), "r"(b1))

#define CP_ASYNC16(saddr, gptr) \
    asm volatile("cp.async.cg.shared.global [%0], [%1], 16;" :: "r"(saddr), "l"(gptr))
#define CP_COMMIT() asm volatile("cp.async.commit_group;" ::: "memory")
#define CP_WAIT1()  asm volatile("cp.async.wait_group 1;" ::: "memory")
#define CP_WAIT0()  asm volatile("cp.async.wait_group 0;" ::: "memory")

// ---------------- prep: convert, norms, inits, label counts ----------------
// grid 2N+1 blocks x 128 thr; block 2N does label counting + scalar inits
__global__ void prep_kernel(const float* __restrict__ a, const float* __restrict__ b,
                            const int* __restrict__ labels) {
    if (blockIdx.x == 2 * N_) {
        __shared__ int sc[16];
        int tid = threadIdx.x;
        if (tid < 16) sc[tid] = 0;
        if (tid == 0) { g_sum = 0.0; g_done = 0; }
        __syncthreads();
        for (int e = tid; e < N_; e += 128) atomicAdd(&sc[labels[e]], 1);
        __syncthreads();
        if (tid < 16) g_cnt[tid] = sc[tid];
        return;
    }
    int r = blockIdx.x & (N_ - 1);
    bool isA = blockIdx.x < N_;
    const float* src = (isA ? a : b) + (size_t)r * F_;
    int tid = threadIdx.x;

    float4 v = ((const float4*)src)[tid];
    unsigned short h[4];
    h[0] = __half_as_ushort(__float2half(v.x));
    h[1] = __half_as_ushort(__float2half(v.y));
    h[2] = __half_as_ushort(__float2half(v.z));
    h[3] = __half_as_ushort(__float2half(v.w));
    ((uint2*)(isA ? g_ah : g_bh))[r * (F_ / 4) + tid] =
        make_uint2(((uint32_t)h[1] << 16) | h[0], ((uint32_t)h[3] << 16) | h[2]);

    float s = v.x * v.x + v.y * v.y + v.z * v.z + v.w * v.w;
#pragma unroll
    for (int o = 16; o; o >>= 1) s += __shfl_xor_sync(0xffffffffu, s, o);
    __shared__ float ws[4];
    int lane = tid & 31, w = tid >> 5;
    if (lane == 0) ws[w] = s;
    __syncthreads();
    if (tid == 0) {
        float t = ws[0] + ws[1] + ws[2] + ws[3];
        if (isA) { g_a2[r] = t; g_negsum[r] = 0.0f; g_poscnt[r] = 0; }
        else g_b2[r] = t;
    }
}

// ---------------- dist kernel ----------------
__device__ __forceinline__ void load_stage(uint32_t sb, uint32_t koff,
                                           const char* baseB, const char* baseA,
                                           const uint32_t* goff, const uint32_t* smoff) {
#pragma unroll
    for (int k = 0; k < 4; ++k) CP_ASYNC16(sb + smoff[k], baseB + goff[k] + koff);
#pragma unroll
    for (int k = 4; k < 8; ++k) CP_ASYNC16(sb + smoff[k], baseA + goff[k] + koff);
}

// store matched (D, j) pairs for one row; warp-uniform call, 4 lanes share a row
__device__ __forceinline__ void flush_pos(int row, unsigned pm, int lane,
                                          const float (&d)[4][2], int colbase) {
    int cnt = __popc(pm);
    unsigned grp = (lane >> 2) << 2;
    int c0 = __shfl_sync(0xffffffffu, cnt, grp);
    int c1 = __shfl_sync(0xffffffffu, cnt, grp + 1);
    int c2 = __shfl_sync(0xffffffffu, cnt, grp + 2);
    int c3 = __shfl_sync(0xffffffffu, cnt, grp + 3);
    int sub = lane & 3;
    int pre = (sub > 0 ? c0 : 0) + (sub > 1 ? c1 : 0) + (sub > 2 ? c2 : 0);
    int tot = c0 + c1 + c2 + c3;
    int base = 0;
    if (sub == 0 && tot > 0) base = atomicAdd(&g_poscnt[row], tot);
    base = __shfl_sync(0xffffffffu, base, grp);
    int off = base + pre;
    float2* dst = g_pos + (size_t)row * PMAX;
#pragma unroll
    for (int an = 0; an < 4; ++an)
#pragma unroll
        for (int cc = 0; cc < 2; ++cc)
            if (pm & (1u << (an * 2 + cc))) {
                dst[off] = make_float2(d[an][cc], __int_as_float(colbase + an * 8 + cc));
                off++;
            }
}

__global__ __launch_bounds__(256, 2)
void dist_kernel(const int* __restrict__ labels) {
    extern __shared__ char smem[];
    const uint32_t sbase = smem_u32(smem);
    const int tid = threadIdx.x;
    const int wid = tid >> 5;
    const int lane = tid & 31;
    const int bi0 = blockIdx.y * TM;
    const int aj0 = blockIdx.x * TNJ;
    const int wm = (wid & 1) * 64;
    const int wn = (wid >> 1) * 32;

    uint32_t goff[8], smoff[8];
#pragma unroll
    for (int t = 0; t < 2; ++t)
#pragma unroll
        for (int q = 0; q < 4; ++q) {
            int linear = tid * 4 + q;
            int r = linear >> 3, cch = linear & 7;
            int row = (t ? aj0 : bi0) + r;
            goff[t * 4 + q] = (uint32_t)(row * (F_ * 2) + cch * 16);
            smoff[t * 4 + q] = (uint32_t)(t * TILE_BYTES + r * 128 + ((cch ^ (r & 7)) << 4));
        }
    const char* baseB = (const char*)g_bh;
    const char* baseA = (const char*)g_ah;

    float acc[4][4][4];
#pragma unroll
    for (int am = 0; am < 4; ++am)
#pragma unroll
        for (int an = 0; an < 4; ++an)
#pragma unroll
            for (int x = 0; x < 4; ++x) acc[am][an][x] = 0.0f;

    load_stage(sbase, 0, baseB, baseA, goff, smoff);                 CP_COMMIT();
    load_stage(sbase + STAGE_BYTES, 128, baseB, baseA, goff, smoff); CP_COMMIT();

    const int lr = lane & 15;
    const int lh = lane >> 4;

#pragma unroll
    for (int c = 0; c < NCH; ++c) {
        if (c < NCH - 1) { CP_WAIT1(); } else { CP_WAIT0(); }
        __syncthreads();
        if (c + 2 < NCH) {
            load_stage(sbase + (uint32_t)((c + 2) % 3) * STAGE_BYTES,
                       (uint32_t)(c + 2) * 128, baseB, baseA, goff, smoff);
            CP_COMMIT();
        }
        uint32_t sb = sbase + (uint32_t)(c % 3) * STAGE_BYTES;

#pragma unroll
        for (int ks = 0; ks < 4; ++ks) {
            uint32_t abh[4][4], bah[2][4];
#pragma unroll
            for (int am = 0; am < 4; ++am) {
                int row = wm + am * 16 + lr;
                uint32_t off = (uint32_t)(row * 128) +
                               (((uint32_t)((ks * 2 + lh) ^ (row & 7))) << 4);
                LDSM4(abh[am], sb + off);
            }
#pragma unroll
            for (int np = 0; np < 2; ++np) {
                int row = wn + np * 16 + lr;
                uint32_t off = (uint32_t)(row * 128) +
                               (((uint32_t)((ks * 2 + lh) ^ (row & 7))) << 4);
                LDSM4(bah[np], sb + TILE_BYTES + off);
            }
#pragma unroll
            for (int am = 0; am < 4; ++am)
#pragma unroll
                for (int an = 0; an < 4; ++an) {
                    uint32_t h0 = bah[an >> 1][an & 1], h1 = bah[an >> 1][(an & 1) + 2];
                    MMA16816(acc[am][an], abh[am], h0, h1);
                }
        }
    }

    // ---------------- epilogue: masked negsum + compact positive-pair store ----------------
    const int lrow2 = lane >> 2;
    const int lcol = (lane & 3) * 2;
    const int colbase = aj0 + wn + lcol;

    float a2c[4][2];
    int lac[4][2];
#pragma unroll
    for (int an = 0; an < 4; ++an) {
        int gj = colbase + an * 8;
        a2c[an][0] = g_a2[gj];     a2c[an][1] = g_a2[gj + 1];
        lac[an][0] = labels[gj];   lac[an][1] = labels[gj + 1];
    }

#pragma unroll
    for (int am = 0; am < 4; ++am) {
        int r0 = bi0 + wm + am * 16 + lrow2;
        int r1 = r0 + 8;
        float b20 = g_b2[r0], b21 = g_b2[r1];
        int lb0 = labels[r0], lb1 = labels[r1];
        float n0 = 0.0f, n1 = 0.0f;
        float d0[4][2], d1[4][2];
        unsigned pm0 = 0, pm1 = 0;
#pragma unroll
        for (int an = 0; an < 4; ++an)
#pragma unroll
            for (int cc = 0; cc < 2; ++cc) {
                int gj = colbase + an * 8 + cc;
                float dd0 = fsqrt_ap(fmaxf(b20 + a2c[an][cc] - 2.0f * acc[am][an][cc], 0.0f));
                d0[an][cc] = dd0;
                if (lac[an][cc] != lb0) n0 += __expf(1.0f - dd0);
                else if (gj != r0) pm0 |= 1u << (an * 2 + cc);
                float dd1 = fsqrt_ap(fmaxf(b21 + a2c[an][cc] - 2.0f * acc[am][an][2 + cc], 0.0f));
                d1[an][cc] = dd1;
                if (lac[an][cc] != lb1) n1 += __expf(1.0f - dd1);
                else if (gj != r1) pm1 |= 1u << (an * 2 + cc);
            }
        n0 += __shfl_xor_sync(0xffffffffu, n0, 1);
        n0 += __shfl_xor_sync(0xffffffffu, n0, 2);
        n1 += __shfl_xor_sync(0xffffffffu, n1, 1);
        n1 += __shfl_xor_sync(0xffffffffu, n1, 2);
        if ((lane & 3) == 0) {
            atomicAdd(&g_negsum[r0], n0);
            atomicAdd(&g_negsum[r1], n1);
        }
        flush_pos(r0, pm0, lane, d0, colbase);
        flush_pos(r1, pm1, lane, d1, colbase);
    }
}

// ---------------- loss: warp per row over compact positive list; last block finalizes ----------------
__global__ void loss_kernel(float* __restrict__ out) {
    int i = blockIdx.x;
    int lane = threadIdx.x;
    int c = g_poscnt[i];
    float nsi = g_negsum[i];
    const float2* pp = g_pos + (size_t)i * PMAX;
    float acc = 0.0f;
    for (int t = lane; t < c; t += 32) {
        float2 p = pp[t];
        int j = __float_as_int(p.y);
        float Jv = __logf(nsi + g_negsum[j]) + p.x;
        float h = fmaxf(Jv, 0.0f);
        acc += h * h;
    }
#pragma unroll
    for (int o = 16; o; o >>= 1) acc += __shfl_xor_sync(0xffffffffu, acc, o);
    if (lane == 0) {
        atomicAdd(&g_sum, (double)acc);
        __threadfence();
        if (atomicAdd(&g_done, 1) == N_ - 1) {
            long long np = 0;
            for (int k = 0; k < 16; ++k) { long long n = g_cnt[k]; np += n * (n - 1); }
            out[0] = (float)(g_sum / (2.0 * (double)np));
        }
    }
}

extern "C" void kernel_launch(void* const* d_in, const int* in_sizes, int n_in,
                              void* d_out, int out_size) {
    const float* a = (const float*)d_in[0];
    const float* b = (const float*)d_in[1];
    const int* labels = (const int*)d_in[2];
    float* out = (float*)d_out;

    cudaFuncSetAttribute(dist_kernel, cudaFuncAttributeMaxDynamicSharedMemorySize, SMEM_TOTAL);

    prep_kernel<<<2 * N_ + 1, 128>>>(a, b, labels);
    dim3 grid(N_ / TNJ, N_ / TM);
    dist_kernel<<<grid, 256, SMEM_TOTAL>>>(labels);
    loss_kernel<<<N_, 32>>>(out);
}

// round 9
// speedup vs baseline: 1.0603x; 1.0603x over previous
#include <cuda_runtime.h>
#include <cuda_fp16.h>
#include <cstdint>
#include <math.h>

#define N_ 4096
#define F_ 512
#define TM 128
#define TNJ 128
#define BK 64
#define NCH (F_ / BK)            // 8 k-chunks
#define TILE_BYTES 16384         // 128 rows x 128B
#define STAGE_BYTES (2 * TILE_BYTES)   // 32KB
#define SMEM_TOTAL (3 * STAGE_BYTES)   // 98304, 2 CTAs/SM
#define PMAX 512                 // slots per row (max class size ~305)

// ---------------- scratch ----------------
__device__ __align__(16) __half g_ah[(size_t)N_ * F_];
__device__ __align__(16) __half g_bh[(size_t)N_ * F_];
__device__ float g_posD[(size_t)N_ * PMAX];   // D for positive pair (i, rank j)
__device__ float g_negsum[N_];
__device__ float g_a2[N_], g_b2[N_];
__device__ int   g_cnt[16];
__device__ int   g_group[16 * N_];   // class -> member rows
__device__ int   g_rank[N_];         // row -> rank within its class
__device__ double g_sum;
__device__ int   g_done;

// ---------------- helpers ----------------
__device__ __forceinline__ uint32_t smem_u32(const void* p) {
    uint32_t r;
    asm("{ .reg .u64 t; cvta.to.shared.u64 t, %1; cvt.u32.u64 %0, t; }" : "=r"(r) : "l"(p));
    return r;
}
__device__ __forceinline__ float fsqrt_ap(float x) {
    float r; asm("sqrt.approx.f32 %0, %1;" : "=f"(r) : "f"(x)); return r;
}

#define LDSM4(r, addr) \
    asm volatile("ldmatrix.sync.aligned.m8n8.x4.shared.b16 {%0,%1,%2,%3}, [%4];" \
                 : "=r"((r)[0]), "=r"((r)[1]), "=r"((r)[2]), "=r"((r)[3]) : "r"(addr))

#define MMA16816(d, a, b0, b1) \
    asm volatile("mma.sync.aligned.m16n8k16.row.col.f32.f16.f16.f32 " \
                 "{%0,%1,%2,%3}, {%4,%5,%6,%7}, {%8,%9}, {%0,%1,%2,%3};" \
                 : "+f"((d)[0]), "+f"((d)[1]), "+f"((d)[2]), "+f"((d)[3]) \
                 : "r"((a)[0]), "r"((a)[1]), "r"((a)[2]), "r"((a)[3]), "r"(b0), "r"(b1))

#define CP_ASYNC16(saddr, gptr) \
    asm volatile("cp.async.cg.shared.global [%0], [%1], 16;" :: "r"(saddr), "l"(gptr))
#define CP_COMMIT() asm volatile("cp.async.commit_group;" ::: "memory")
#define CP_WAIT1()  asm volatile("cp.async.wait_group 1;" ::: "memory")
#define CP_WAIT0()  asm volatile("cp.async.wait_group 0;" ::: "memory")

// ---------------- prep: warp-per-row convert+norm; last block groups ----------------
// grid = 1025 blocks x 256 thr. Blocks 0..1023: 8 warps x 1 row each (8192 rows).
__global__ void prep_kernel(const float* __restrict__ a, const float* __restrict__ b,
                            const int* __restrict__ labels) {
    int tid = threadIdx.x;
    if (blockIdx.x == 1024) {
        __shared__ int sc[16];
        if (tid < 16) sc[tid] = 0;
        if (tid == 0) { g_sum = 0.0; g_done = 0; }
        __syncthreads();
        for (int e = tid; e < N_; e += 256) {
            int c = labels[e];
            int s = atomicAdd(&sc[c], 1);
            g_group[c * N_ + s] = e;
            g_rank[e] = s;
        }
        __syncthreads();
        if (tid < 16) g_cnt[tid] = sc[tid];
        return;
    }
    int warp = tid >> 5, lane = tid & 31;
    int gr = blockIdx.x * 8 + warp;          // 0..8191
    int r = gr & (N_ - 1);
    bool isA = gr < N_;
    const float4* src = (const float4*)((isA ? a : b) + (size_t)r * F_);
    uint2* dst = (uint2*)(isA ? g_ah : g_bh) + r * (F_ / 4);

    float s = 0.0f;
#pragma unroll
    for (int q = 0; q < 4; ++q) {
        float4 v = src[lane + 32 * q];
        unsigned short h0 = __half_as_ushort(__float2half(v.x));
        unsigned short h1 = __half_as_ushort(__float2half(v.y));
        unsigned short h2 = __half_as_ushort(__float2half(v.z));
        unsigned short h3 = __half_as_ushort(__float2half(v.w));
        dst[lane + 32 * q] = make_uint2(((uint32_t)h1 << 16) | h0,
                                        ((uint32_t)h3 << 16) | h2);
        s += v.x * v.x + v.y * v.y + v.z * v.z + v.w * v.w;
    }
#pragma unroll
    for (int o = 16; o; o >>= 1) s += __shfl_xor_sync(0xffffffffu, s, o);
    if (lane == 0) {
        if (isA) { g_a2[r] = s; g_negsum[r] = 0.0f; }
        else g_b2[r] = s;
    }
}

// ---------------- dist kernel ----------------
__device__ __forceinline__ void load_stage(uint32_t sb, uint32_t koff,
                                           const char* baseB, const char* baseA,
                                           const uint32_t* goff, const uint32_t* smoff) {
#pragma unroll
    for (int k = 0; k < 4; ++k) CP_ASYNC16(sb + smoff[k], baseB + goff[k] + koff);
#pragma unroll
    for (int k = 4; k < 8; ++k) CP_ASYNC16(sb + smoff[k], baseA + goff[k] + koff);
}

__global__ __launch_bounds__(256, 2)
void dist_kernel(const int* __restrict__ labels) {
    extern __shared__ char smem[];
    const uint32_t sbase = smem_u32(smem);
    const int tid = threadIdx.x;
    const int wid = tid >> 5;
    const int lane = tid & 31;
    const int bi0 = blockIdx.y * TM;
    const int aj0 = blockIdx.x * TNJ;
    const int wm = (wid & 1) * 64;
    const int wn = (wid >> 1) * 32;

    uint32_t goff[8], smoff[8];
#pragma unroll
    for (int t = 0; t < 2; ++t)
#pragma unroll
        for (int q = 0; q < 4; ++q) {
            int linear = tid * 4 + q;
            int r = linear >> 3, cch = linear & 7;
            int row = (t ? aj0 : bi0) + r;
            goff[t * 4 + q] = (uint32_t)(row * (F_ * 2) + cch * 16);
            smoff[t * 4 + q] = (uint32_t)(t * TILE_BYTES + r * 128 + ((cch ^ (r & 7)) << 4));
        }
    const char* baseB = (const char*)g_bh;
    const char* baseA = (const char*)g_ah;

    float acc[4][4][4];
#pragma unroll
    for (int am = 0; am < 4; ++am)
#pragma unroll
        for (int an = 0; an < 4; ++an)
#pragma unroll
            for (int x = 0; x < 4; ++x) acc[am][an][x] = 0.0f;

    load_stage(sbase, 0, baseB, baseA, goff, smoff);                 CP_COMMIT();
    load_stage(sbase + STAGE_BYTES, 128, baseB, baseA, goff, smoff); CP_COMMIT();

    const int lr = lane & 15;
    const int lh = lane >> 4;

#pragma unroll
    for (int c = 0; c < NCH; ++c) {
        if (c < NCH - 1) { CP_WAIT1(); } else { CP_WAIT0(); }
        __syncthreads();
        if (c + 2 < NCH) {
            load_stage(sbase + (uint32_t)((c + 2) % 3) * STAGE_BYTES,
                       (uint32_t)(c + 2) * 128, baseB, baseA, goff, smoff);
            CP_COMMIT();
        }
        uint32_t sb = sbase + (uint32_t)(c % 3) * STAGE_BYTES;

#pragma unroll
        for (int ks = 0; ks < 4; ++ks) {
            uint32_t abh[4][4], bah[2][4];
#pragma unroll
            for (int am = 0; am < 4; ++am) {
                int row = wm + am * 16 + lr;
                uint32_t off = (uint32_t)(row * 128) +
                               (((uint32_t)((ks * 2 + lh) ^ (row & 7))) << 4);
                LDSM4(abh[am], sb + off);
            }
#pragma unroll
            for (int np = 0; np < 2; ++np) {
                int row = wn + np * 16 + lr;
                uint32_t off = (uint32_t)(row * 128) +
                               (((uint32_t)((ks * 2 + lh) ^ (row & 7))) << 4);
                LDSM4(bah[np], sb + TILE_BYTES + off);
            }
#pragma unroll
            for (int am = 0; am < 4; ++am)
#pragma unroll
                for (int an = 0; an < 4; ++an) {
                    uint32_t h0 = bah[an >> 1][an & 1], h1 = bah[an >> 1][(an & 1) + 2];
                    MMA16816(acc[am][an], abh[am], h0, h1);
                }
        }
    }

    // ---------------- epilogue: masked negsum + rank-slot positive store ----------------
    const int lrow2 = lane >> 2;
    const int lcol = (lane & 3) * 2;
    const int colbase = aj0 + wn + lcol;

    float a2c[4][2];
    int lac[4][2], rnk[4][2];
#pragma unroll
    for (int an = 0; an < 4; ++an) {
        int gj = colbase + an * 8;
        a2c[an][0] = g_a2[gj];     a2c[an][1] = g_a2[gj + 1];
        lac[an][0] = labels[gj];   lac[an][1] = labels[gj + 1];
        rnk[an][0] = g_rank[gj];   rnk[an][1] = g_rank[gj + 1];
    }

#pragma unroll
    for (int am = 0; am < 4; ++am) {
        int r0 = bi0 + wm + am * 16 + lrow2;
        int r1 = r0 + 8;
        float b20 = g_b2[r0], b21 = g_b2[r1];
        int lb0 = labels[r0], lb1 = labels[r1];
        float* p0 = g_posD + (size_t)r0 * PMAX;
        float* p1 = g_posD + (size_t)r1 * PMAX;
        float n0 = 0.0f, n1 = 0.0f;
#pragma unroll
        for (int an = 0; an < 4; ++an)
#pragma unroll
            for (int cc = 0; cc < 2; ++cc) {
                int gj = colbase + an * 8 + cc;
                float dd0 = fsqrt_ap(fmaxf(b20 + a2c[an][cc] - 2.0f * acc[am][an][cc], 0.0f));
                if (lac[an][cc] != lb0) n0 += __expf(1.0f - dd0);
                else if (gj != r0) p0[rnk[an][cc]] = dd0;
                float dd1 = fsqrt_ap(fmaxf(b21 + a2c[an][cc] - 2.0f * acc[am][an][2 + cc], 0.0f));
                if (lac[an][cc] != lb1) n1 += __expf(1.0f - dd1);
                else if (gj != r1) p1[rnk[an][cc]] = dd1;
            }
        n0 += __shfl_xor_sync(0xffffffffu, n0, 1);
        n0 += __shfl_xor_sync(0xffffffffu, n0, 2);
        n1 += __shfl_xor_sync(0xffffffffu, n1, 1);
        n1 += __shfl_xor_sync(0xffffffffu, n1, 2);
        if ((lane & 3) == 0) {
            atomicAdd(&g_negsum[r0], n0);
            atomicAdd(&g_negsum[r1], n1);
        }
    }
}

// ---------------- loss: warp per row over rank-ordered slab; last block finalizes ----------------
__global__ void loss_kernel(const int* __restrict__ labels, float* __restrict__ out) {
    int i = blockIdx.x;
    int lane = threadIdx.x;
    int c = labels[i];
    int n = g_cnt[c];
    int ri = g_rank[i];
    float nsi = g_negsum[i];
    const float* pD = g_posD + (size_t)i * PMAX;
    const int* grp = g_group + c * N_;
    float acc = 0.0f;
    for (int t = lane; t < n; t += 32) {
        if (t == ri) continue;
        int j = grp[t];
        float Jv = __logf(nsi + g_negsum[j]) + pD[t];
        float h = fmaxf(Jv, 0.0f);
        acc += h * h;
    }
#pragma unroll
    for (int o = 16; o; o >>= 1) acc += __shfl_xor_sync(0xffffffffu, acc, o);
    if (lane == 0) {
        atomicAdd(&g_sum, (double)acc);
        __threadfence();
        if (atomicAdd(&g_done, 1) == N_ - 1) {
            long long np = 0;
            for (int k = 0; k < 16; ++k) { long long nn = g_cnt[k]; np += nn * (nn - 1); }
            out[0] = (float)(g_sum / (2.0 * (double)np));
        }
    }
}

extern "C" void kernel_launch(void* const* d_in, const int* in_sizes, int n_in,
                              void* d_out, int out_size) {
    const float* a = (const float*)d_in[0];
    const float* b = (const float*)d_in[1];
    const int* labels = (const int*)d_in[2];
    float* out = (float*)d_out;

    cudaFuncSetAttribute(dist_kernel, cudaFuncAttributeMaxDynamicSharedMemorySize, SMEM_TOTAL);

    prep_kernel<<<1025, 256>>>(a, b, labels);
    dim3 grid(N_ / TNJ, N_ / TM);
    dist_kernel<<<grid, 256, SMEM_TOTAL>>>(labels);
    loss_kernel<<<N_, 32>>>(labels, out);
}

// round 10
// speedup vs baseline: 1.1147x; 1.0514x over previous
#include <cuda_runtime.h>
#include <cuda_fp16.h>
#include <cstdint>
#include <math.h>

#define N_ 4096
#define F_ 512
#define TM 128
#define TNJ 128
#define BK 64
#define NCH (F_ / BK)            // 8 k-chunks
#define TILE_BYTES 16384         // 128 rows x 128B
#define STAGE_BYTES (2 * TILE_BYTES)   // 32KB
#define SMEM_TOTAL (3 * STAGE_BYTES)   // 98304, 2 CTAs/SM
#define PMAX 512                 // slots per row (max class size ~305)

// ---------------- scratch ----------------
__device__ __align__(16) __half g_ah[(size_t)N_ * F_];   // permuted rows
__device__ __align__(16) __half g_bh[(size_t)N_ * F_];   // permuted rows
__device__ float g_posD[(size_t)N_ * PMAX];   // D[perm_i][rank_j] for positives
__device__ float g_negsum[N_];                // permuted space
__device__ float g_a2[N_], g_b2[N_];          // permuted space
__device__ int   g_meta[N_];                  // (cls<<16)|rank per permuted index
__device__ int   g_permpos[N_];               // original row -> permuted position
__device__ int   g_cnt[16];
__device__ int   g_start[16];
__device__ double g_sum;
__device__ int   g_done;

// ---------------- helpers ----------------
__device__ __forceinline__ uint32_t smem_u32(const void* p) {
    uint32_t r;
    asm("{ .reg .u64 t; cvta.to.shared.u64 t, %1; cvt.u32.u64 %0, t; }" : "=r"(r) : "l"(p));
    return r;
}
__device__ __forceinline__ float fsqrt_ap(float x) {
    float r; asm("sqrt.approx.f32 %0, %1;" : "=f"(r) : "f"(x)); return r;
}

#define LDSM4(r, addr) \
    asm volatile("ldmatrix.sync.aligned.m8n8.x4.shared.b16 {%0,%1,%2,%3}, [%4];" \
                 : "=r"((r)[0]), "=r"((r)[1]), "=r"((r)[2]), "=r"((r)[3]) : "r"(addr))

#define MMA16816(d, a, b0, b1) \
    asm volatile("mma.sync.aligned.m16n8k16.row.col.f32.f16.f16.f32 " \
                 "{%0,%1,%2,%3}, {%4,%5,%6,%7}, {%8,%9}, {%0,%1,%2,%3};" \
                 : "+f"((d)[0]), "+f"((d)[1]), "+f"((d)[2]), "+f"((d)[3]) \
                 : "r"((a)[0]), "r"((a)[1]), "r"((a)[2]), "r"((a)[3]), "r"(b0), "r"(b1))

#define CP_ASYNC16(saddr, gptr) \
    asm volatile("cp.async.cg.shared.global [%0], [%1], 16;" :: "r"(saddr), "l"(gptr))
#define CP_COMMIT() asm volatile("cp.async.commit_group;" ::: "memory")
#define CP_WAIT1()  asm volatile("cp.async.wait_group 1;" ::: "memory")
#define CP_WAIT0()  asm volatile("cp.async.wait_group 0;" ::: "memory")

// ---------------- perm: class-sort permutation, meta, counts (1 block) ----------------
__global__ void perm_kernel(const int* __restrict__ labels) {
    __shared__ int sc[16], sstart[16];
    int tid = threadIdx.x;
    if (tid < 16) sc[tid] = 0;
    if (tid == 0) { g_sum = 0.0; g_done = 0; }
    __syncthreads();
    for (int e = tid; e < N_; e += blockDim.x) atomicAdd(&sc[labels[e]], 1);
    __syncthreads();
    if (tid == 0) {
        int acc = 0;
        for (int c = 0; c < 16; ++c) { sstart[c] = acc; g_start[c] = acc;
                                       g_cnt[c] = sc[c]; acc += sc[c]; }
    }
    __syncthreads();
    if (tid < 16) sc[tid] = 0;
    __syncthreads();
    for (int e = tid; e < N_; e += blockDim.x) {
        int c = labels[e];
        int r = atomicAdd(&sc[c], 1);
        int pos = sstart[c] + r;
        g_permpos[e] = pos;
        g_meta[pos] = (c << 16) | r;
    }
}

// ---------------- prep: convert+norm at permuted positions ----------------
// grid 2N x 128 thr; block r<N -> a-row r, else b-row
__global__ void prep_kernel(const float* __restrict__ a, const float* __restrict__ b) {
    int r = blockIdx.x & (N_ - 1);
    bool isA = blockIdx.x < N_;
    int pos = g_permpos[r];
    const float* src = (isA ? a : b) + (size_t)r * F_;
    int tid = threadIdx.x;

    float4 v = ((const float4*)src)[tid];
    unsigned short h0 = __half_as_ushort(__float2half(v.x));
    unsigned short h1 = __half_as_ushort(__float2half(v.y));
    unsigned short h2 = __half_as_ushort(__float2half(v.z));
    unsigned short h3 = __half_as_ushort(__float2half(v.w));
    ((uint2*)(isA ? g_ah : g_bh))[pos * (F_ / 4) + tid] =
        make_uint2(((uint32_t)h1 << 16) | h0, ((uint32_t)h3 << 16) | h2);

    float s = v.x * v.x + v.y * v.y + v.z * v.z + v.w * v.w;
#pragma unroll
    for (int o = 16; o; o >>= 1) s += __shfl_xor_sync(0xffffffffu, s, o);
    __shared__ float ws[4];
    int lane = tid & 31, w = tid >> 5;
    if (lane == 0) ws[w] = s;
    __syncthreads();
    if (tid == 0) {
        float t = ws[0] + ws[1] + ws[2] + ws[3];
        if (isA) { g_a2[pos] = t; g_negsum[pos] = 0.0f; }
        else g_b2[pos] = t;
    }
}

// ---------------- dist kernel ----------------
__device__ __forceinline__ void load_stage(uint32_t sb, uint32_t koff,
                                           const char* baseB, const char* baseA,
                                           const uint32_t* goff, const uint32_t* smoff) {
#pragma unroll
    for (int k = 0; k < 4; ++k) CP_ASYNC16(sb + smoff[k], baseB + goff[k] + koff);
#pragma unroll
    for (int k = 4; k < 8; ++k) CP_ASYNC16(sb + smoff[k], baseA + goff[k] + koff);
}

__global__ __launch_bounds__(256, 2)
void dist_kernel() {
    extern __shared__ char smem[];
    const uint32_t sbase = smem_u32(smem);
    const int tid = threadIdx.x;
    const int wid = tid >> 5;
    const int lane = tid & 31;
    const int bi0 = blockIdx.y * TM;
    const int aj0 = blockIdx.x * TNJ;
    const int wm = (wid & 1) * 64;
    const int wn = (wid >> 1) * 32;

    uint32_t goff[8], smoff[8];
#pragma unroll
    for (int t = 0; t < 2; ++t)
#pragma unroll
        for (int q = 0; q < 4; ++q) {
            int linear = tid * 4 + q;
            int r = linear >> 3, cch = linear & 7;
            int row = (t ? aj0 : bi0) + r;
            goff[t * 4 + q] = (uint32_t)(row * (F_ * 2) + cch * 16);
            smoff[t * 4 + q] = (uint32_t)(t * TILE_BYTES + r * 128 + ((cch ^ (r & 7)) << 4));
        }
    const char* baseB = (const char*)g_bh;
    const char* baseA = (const char*)g_ah;

    float acc[4][4][4];
#pragma unroll
    for (int am = 0; am < 4; ++am)
#pragma unroll
        for (int an = 0; an < 4; ++an)
#pragma unroll
            for (int x = 0; x < 4; ++x) acc[am][an][x] = 0.0f;

    load_stage(sbase, 0, baseB, baseA, goff, smoff);                 CP_COMMIT();
    load_stage(sbase + STAGE_BYTES, 128, baseB, baseA, goff, smoff); CP_COMMIT();

    const int lr = lane & 15;
    const int lh = lane >> 4;

#pragma unroll
    for (int c = 0; c < NCH; ++c) {
        if (c < NCH - 1) { CP_WAIT1(); } else { CP_WAIT0(); }
        __syncthreads();
        if (c + 2 < NCH) {
            load_stage(sbase + (uint32_t)((c + 2) % 3) * STAGE_BYTES,
                       (uint32_t)(c + 2) * 128, baseB, baseA, goff, smoff);
            CP_COMMIT();
        }
        uint32_t sb = sbase + (uint32_t)(c % 3) * STAGE_BYTES;

#pragma unroll
        for (int ks = 0; ks < 4; ++ks) {
            uint32_t abh[4][4], bah[2][4];
#pragma unroll
            for (int am = 0; am < 4; ++am) {
                int row = wm + am * 16 + lr;
                uint32_t off = (uint32_t)(row * 128) +
                               (((uint32_t)((ks * 2 + lh) ^ (row & 7))) << 4);
                LDSM4(abh[am], sb + off);
            }
#pragma unroll
            for (int np = 0; np < 2; ++np) {
                int row = wn + np * 16 + lr;
                uint32_t off = (uint32_t)(row * 128) +
                               (((uint32_t)((ks * 2 + lh) ^ (row & 7))) << 4);
                LDSM4(bah[np], sb + TILE_BYTES + off);
            }
#pragma unroll
            for (int am = 0; am < 4; ++am)
#pragma unroll
                for (int an = 0; an < 4; ++an) {
                    uint32_t h0 = bah[an >> 1][an & 1], h1 = bah[an >> 1][(an & 1) + 2];
                    MMA16816(acc[am][an], abh[am], h0, h1);
                }
        }
    }

    // ------- epilogue: masked negsum + contiguous-window positive store -------
    const int lrow2 = lane >> 2;
    const int lcol = (lane & 3) * 2;
    const int colbase = aj0 + wn + lcol;

    float a2c[4][2];
    int cm[4][2];                 // (cls<<16)|rank per column
#pragma unroll
    for (int an = 0; an < 4; ++an) {
        int gj = colbase + an * 8;
        a2c[an][0] = g_a2[gj];   a2c[an][1] = g_a2[gj + 1];
        cm[an][0] = g_meta[gj];  cm[an][1] = g_meta[gj + 1];
    }

#pragma unroll
    for (int am = 0; am < 4; ++am) {
        int r0 = bi0 + wm + am * 16 + lrow2;
        int r1 = r0 + 8;
        float b20 = g_b2[r0], b21 = g_b2[r1];
        int cl0 = g_meta[r0] >> 16, cl1 = g_meta[r1] >> 16;
        float* p0 = g_posD + (size_t)r0 * PMAX;
        float* p1 = g_posD + (size_t)r1 * PMAX;
        float n0 = 0.0f, n1 = 0.0f;
#pragma unroll
        for (int an = 0; an < 4; ++an)
#pragma unroll
            for (int cc = 0; cc < 2; ++cc) {
                int gj = colbase + an * 8 + cc;
                int cls = cm[an][cc] >> 16, rnk = cm[an][cc] & 0xffff;
                float dd0 = fsqrt_ap(fmaxf(b20 + a2c[an][cc] - 2.0f * acc[am][an][cc], 0.0f));
                if (cls != cl0) n0 += __expf(1.0f - dd0);
                else if (gj != r0) p0[rnk] = dd0;
                float dd1 = fsqrt_ap(fmaxf(b21 + a2c[an][cc] - 2.0f * acc[am][an][2 + cc], 0.0f));
                if (cls != cl1) n1 += __expf(1.0f - dd1);
                else if (gj != r1) p1[rnk] = dd1;
            }
        n0 += __shfl_xor_sync(0xffffffffu, n0, 1);
        n0 += __shfl_xor_sync(0xffffffffu, n0, 2);
        n1 += __shfl_xor_sync(0xffffffffu, n1, 1);
        n1 += __shfl_xor_sync(0xffffffffu, n1, 2);
        if ((lane & 3) == 0) {
            atomicAdd(&g_negsum[r0], n0);
            atomicAdd(&g_negsum[r1], n1);
        }
    }
}

// ---------------- loss: warp per permuted row; contiguous window; last block finalizes ----------------
__global__ void loss_kernel(float* __restrict__ out) {
    int i = blockIdx.x;
    int lane = threadIdx.x;
    int m = g_meta[i];
    int c = m >> 16, ri = m & 0xffff;
    int s = g_start[c], n = g_cnt[c];
    float nsi = g_negsum[i];
    const float* pD = g_posD + (size_t)i * PMAX;
    const float* ns = g_negsum + s;
    float acc = 0.0f;
    for (int t = lane; t < n; t += 32) {
        if (t == ri) continue;
        float Jv = __logf(nsi + ns[t]) + pD[t];
        float h = fmaxf(Jv, 0.0f);
        acc += h * h;
    }
#pragma unroll
    for (int o = 16; o; o >>= 1) acc += __shfl_xor_sync(0xffffffffu, acc, o);
    if (lane == 0) {
        atomicAdd(&g_sum, (double)acc);
        __threadfence();
        if (atomicAdd(&g_done, 1) == N_ - 1) {
            long long np = 0;
            for (int k = 0; k < 16; ++k) { long long nn = g_cnt[k]; np += nn * (nn - 1); }
            out[0] = (float)(g_sum / (2.0 * (double)np));
        }
    }
}

extern "C" void kernel_launch(void* const* d_in, const int* in_sizes, int n_in,
                              void* d_out, int out_size) {
    const float* a = (const float*)d_in[0];
    const float* b = (const float*)d_in[1];
    const int* labels = (const int*)d_in[2];
    float* out = (float*)d_out;

    cudaFuncSetAttribute(dist_kernel, cudaFuncAttributeMaxDynamicSharedMemorySize, SMEM_TOTAL);

    perm_kernel<<<1, 1024>>>(labels);
    prep_kernel<<<2 * N_, 128>>>(a, b);
    dim3 grid(N_ / TNJ, N_ / TM);
    dist_kernel<<<grid, 256, SMEM_TOTAL>>>();
    loss_kernel<<<N_, 32>>>(out);
}

// round 11
// speedup vs baseline: 1.1801x; 1.0586x over previous
#include <cuda_runtime.h>
#include <cuda_fp16.h>
#include <cstdint>
#include <math.h>

#define N_ 4096
#define F_ 512
#define TM 128
#define TNJ 128
#define BK 64
#define NCH (F_ / BK)            // 8 k-chunks
#define TILE_BYTES 16384         // 128 rows x 128B
#define STAGE_BYTES (2 * TILE_BYTES)   // 32KB
#define SMEM_TOTAL (3 * STAGE_BYTES)   // 98304, 2 CTAs/SM
#define PMAX 512                 // slots per row (max class size ~305)

// ---------------- scratch ----------------
__device__ __align__(16) __half g_ah[(size_t)N_ * F_];   // permuted rows
__device__ __align__(16) __half g_bh[(size_t)N_ * F_];   // permuted rows
__device__ float g_posD[(size_t)N_ * PMAX];   // D[perm_i][rank_j] for positives
__device__ float g_negsum[N_];                // permuted space
__device__ float g_a2[N_], g_b2[N_];          // permuted space
__device__ int   g_meta[N_];                  // (cls<<16)|rank per permuted index
__device__ int   g_permpos[N_];               // original row -> permuted position
__device__ int   g_cnt[16];
__device__ int   g_start[16];
__device__ double g_sum;
__device__ int   g_done;

// ---------------- helpers ----------------
__device__ __forceinline__ uint32_t smem_u32(const void* p) {
    uint32_t r;
    asm("{ .reg .u64 t; cvta.to.shared.u64 t, %1; cvt.u32.u64 %0, t; }" : "=r"(r) : "l"(p));
    return r;
}
__device__ __forceinline__ float fsqrt_ap(float x) {
    float r; asm("sqrt.approx.f32 %0, %1;" : "=f"(r) : "f"(x)); return r;
}

#define LDSM4(r, addr) \
    asm volatile("ldmatrix.sync.aligned.m8n8.x4.shared.b16 {%0,%1,%2,%3}, [%4];" \
                 : "=r"((r)[0]), "=r"((r)[1]), "=r"((r)[2]), "=r"((r)[3]) : "r"(addr))

#define MMA16816(d, a, b0, b1) \
    asm volatile("mma.sync.aligned.m16n8k16.row.col.f32.f16.f16.f32 " \
                 "{%0,%1,%2,%3}, {%4,%5,%6,%7}, {%8,%9}, {%0,%1,%2,%3};" \
                 : "+f"((d)[0]), "+f"((d)[1]), "+f"((d)[2]), "+f"((d)[3]) \
                 : "r"((a)[0]), "r"((a)[1]), "r"((a)[2]), "r"((a)[3]), "r"(b0), "r"(b1))

#define CP_ASYNC16(saddr, gptr) \
    asm volatile("cp.async.cg.shared.global [%0], [%1], 16;" :: "r"(saddr), "l"(gptr))
#define CP_COMMIT() asm volatile("cp.async.commit_group;" ::: "memory")
#define CP_WAIT1()  asm volatile("cp.async.wait_group 1;" ::: "memory")
#define CP_WAIT0()  asm volatile("cp.async.wait_group 0;" ::: "memory")

// ---------------- perm: class-sort permutation, meta, counts (1 block) ----------------
__global__ void perm_kernel(const int* __restrict__ labels) {
    __shared__ int sc[16], sstart[16];
    int tid = threadIdx.x;
    if (tid < 16) sc[tid] = 0;
    if (tid == 0) { g_sum = 0.0; g_done = 0; }
    __syncthreads();
    for (int e = tid; e < N_; e += blockDim.x) atomicAdd(&sc[labels[e]], 1);
    __syncthreads();
    if (tid == 0) {
        int acc = 0;
        for (int c = 0; c < 16; ++c) { sstart[c] = acc; g_start[c] = acc;
                                       g_cnt[c] = sc[c]; acc += sc[c]; }
    }
    __syncthreads();
    if (tid < 16) sc[tid] = 0;
    __syncthreads();
    for (int e = tid; e < N_; e += blockDim.x) {
        int c = labels[e];
        int r = atomicAdd(&sc[c], 1);
        int pos = sstart[c] + r;
        g_permpos[e] = pos;
        g_meta[pos] = (c << 16) | r;
    }
}

// ---------------- prep: convert+norm at permuted positions ----------------
// grid 2N x 128 thr; block r<N -> a-row r, else b-row
__global__ void prep_kernel(const float* __restrict__ a, const float* __restrict__ b) {
    int r = blockIdx.x & (N_ - 1);
    bool isA = blockIdx.x < N_;
    int pos = g_permpos[r];
    const float* src = (isA ? a : b) + (size_t)r * F_;
    int tid = threadIdx.x;

    float4 v = ((const float4*)src)[tid];
    unsigned short h0 = __half_as_ushort(__float2half(v.x));
    unsigned short h1 = __half_as_ushort(__float2half(v.y));
    unsigned short h2 = __half_as_ushort(__float2half(v.z));
    unsigned short h3 = __half_as_ushort(__float2half(v.w));
    ((uint2*)(isA ? g_ah : g_bh))[pos * (F_ / 4) + tid] =
        make_uint2(((uint32_t)h1 << 16) | h0, ((uint32_t)h3 << 16) | h2);

    float s = v.x * v.x + v.y * v.y + v.z * v.z + v.w * v.w;
#pragma unroll
    for (int o = 16; o; o >>= 1) s += __shfl_xor_sync(0xffffffffu, s, o);
    __shared__ float ws[4];
    int lane = tid & 31, w = tid >> 5;
    if (lane == 0) ws[w] = s;
    __syncthreads();
    if (tid == 0) {
        float t = ws[0] + ws[1] + ws[2] + ws[3];
        if (isA) { g_a2[pos] = t; g_negsum[pos] = 0.0f; }
        else g_b2[pos] = t;
    }
}

// ---------------- dist kernel ----------------
__device__ __forceinline__ void load_stage(uint32_t sb, uint32_t koff,
                                           const char* baseB, const char* baseA,
                                           const uint32_t* goff, const uint32_t* smoff) {
#pragma unroll
    for (int k = 0; k < 4; ++k) CP_ASYNC16(sb + smoff[k], baseB + goff[k] + koff);
#pragma unroll
    for (int k = 4; k < 8; ++k) CP_ASYNC16(sb + smoff[k], baseA + goff[k] + koff);
}

__global__ __launch_bounds__(256, 2)
void dist_kernel() {
    extern __shared__ char smem[];
    const uint32_t sbase = smem_u32(smem);
    const int tid = threadIdx.x;
    const int wid = tid >> 5;
    const int lane = tid & 31;
    const int bi0 = blockIdx.y * TM;
    const int aj0 = blockIdx.x * TNJ;
    const int wm = (wid & 1) * 64;
    const int wn = (wid >> 1) * 32;

    uint32_t goff[8], smoff[8];
#pragma unroll
    for (int t = 0; t < 2; ++t)
#pragma unroll
        for (int q = 0; q < 4; ++q) {
            int linear = tid * 4 + q;
            int r = linear >> 3, cch = linear & 7;
            int row = (t ? aj0 : bi0) + r;
            goff[t * 4 + q] = (uint32_t)(row * (F_ * 2) + cch * 16);
            smoff[t * 4 + q] = (uint32_t)(t * TILE_BYTES + r * 128 + ((cch ^ (r & 7)) << 4));
        }
    const char* baseB = (const char*)g_bh;
    const char* baseA = (const char*)g_ah;

    float acc[4][4][4];
#pragma unroll
    for (int am = 0; am < 4; ++am)
#pragma unroll
        for (int an = 0; an < 4; ++an)
#pragma unroll
            for (int x = 0; x < 4; ++x) acc[am][an][x] = 0.0f;

    load_stage(sbase, 0, baseB, baseA, goff, smoff);                 CP_COMMIT();
    load_stage(sbase + STAGE_BYTES, 128, baseB, baseA, goff, smoff); CP_COMMIT();

    const int lr = lane & 15;
    const int lh = lane >> 4;

#pragma unroll
    for (int c = 0; c < NCH; ++c) {
        if (c < NCH - 1) { CP_WAIT1(); } else { CP_WAIT0(); }
        __syncthreads();
        if (c + 2 < NCH) {
            load_stage(sbase + (uint32_t)((c + 2) % 3) * STAGE_BYTES,
                       (uint32_t)(c + 2) * 128, baseB, baseA, goff, smoff);
            CP_COMMIT();
        }
        uint32_t sb = sbase + (uint32_t)(c % 3) * STAGE_BYTES;

#pragma unroll
        for (int ks = 0; ks < 4; ++ks) {
            uint32_t abh[4][4], bah[2][4];
#pragma unroll
            for (int am = 0; am < 4; ++am) {
                int row = wm + am * 16 + lr;
                uint32_t off = (uint32_t)(row * 128) +
                               (((uint32_t)((ks * 2 + lh) ^ (row & 7))) << 4);
                LDSM4(abh[am], sb + off);
            }
#pragma unroll
            for (int np = 0; np < 2; ++np) {
                int row = wn + np * 16 + lr;
                uint32_t off = (uint32_t)(row * 128) +
                               (((uint32_t)((ks * 2 + lh) ^ (row & 7))) << 4);
                LDSM4(bah[np], sb + TILE_BYTES + off);
            }
#pragma unroll
            for (int am = 0; am < 4; ++am)
#pragma unroll
                for (int an = 0; an < 4; ++an) {
                    uint32_t h0 = bah[an >> 1][an & 1], h1 = bah[an >> 1][(an & 1) + 2];
                    MMA16816(acc[am][an], abh[am], h0, h1);
                }
        }
    }

    // ------- epilogue: masked negsum + contiguous-window positive store -------
    const int lrow2 = lane >> 2;
    const int lcol = (lane & 3) * 2;
    const int colbase = aj0 + wn + lcol;

    float a2c[4][2];
    int cm[4][2];                 // (cls<<16)|rank per column
#pragma unroll
    for (int an = 0; an < 4; ++an) {
        int gj = colbase + an * 8;
        a2c[an][0] = g_a2[gj];   a2c[an][1] = g_a2[gj + 1];
        cm[an][0] = g_meta[gj];  cm[an][1] = g_meta[gj + 1];
    }

#pragma unroll
    for (int am = 0; am < 4; ++am) {
        int r0 = bi0 + wm + am * 16 + lrow2;
        int r1 = r0 + 8;
        float b20 = g_b2[r0], b21 = g_b2[r1];
        int cl0 = g_meta[r0] >> 16, cl1 = g_meta[r1] >> 16;
        float* p0 = g_posD + (size_t)r0 * PMAX;
        float* p1 = g_posD + (size_t)r1 * PMAX;
        float n0 = 0.0f, n1 = 0.0f;
#pragma unroll
        for (int an = 0; an < 4; ++an)
#pragma unroll
            for (int cc = 0; cc < 2; ++cc) {
                int gj = colbase + an * 8 + cc;
                int cls = cm[an][cc] >> 16, rnk = cm[an][cc] & 0xffff;
                float dd0 = fsqrt_ap(fmaxf(b20 + a2c[an][cc] - 2.0f * acc[am][an][cc], 0.0f));
                if (cls != cl0) n0 += __expf(1.0f - dd0);
                else if (gj != r0) p0[rnk] = dd0;
                float dd1 = fsqrt_ap(fmaxf(b21 + a2c[an][cc] - 2.0f * acc[am][an][2 + cc], 0.0f));
                if (cls != cl1) n1 += __expf(1.0f - dd1);
                else if (gj != r1) p1[rnk] = dd1;
            }
        n0 += __shfl_xor_sync(0xffffffffu, n0, 1);
        n0 += __shfl_xor_sync(0xffffffffu, n0, 2);
        n1 += __shfl_xor_sync(0xffffffffu, n1, 1);
        n1 += __shfl_xor_sync(0xffffffffu, n1, 2);
        if ((lane & 3) == 0) {
            atomicAdd(&g_negsum[r0], n0);
            atomicAdd(&g_negsum[r1], n1);
        }
    }
}

// ---------------- loss: 256-thr blocks, warp per row (8 rows/block); last block finalizes ----------------
__global__ __launch_bounds__(256)
void loss_kernel(float* __restrict__ out) {
    int lane = threadIdx.x & 31;
    int warp = threadIdx.x >> 5;
    int i = blockIdx.x * 8 + warp;
    int m = g_meta[i];
    int c = m >> 16, ri = m & 0xffff;
    int s = g_start[c], n = g_cnt[c];
    float nsi = g_negsum[i];
    const float* pD = g_posD + (size_t)i * PMAX;
    const float* ns = g_negsum + s;
    float acc = 0.0f;
    for (int t = lane; t < n; t += 32) {
        if (t == ri) continue;
        float Jv = __logf(nsi + ns[t]) + pD[t];
        float h = fmaxf(Jv, 0.0f);
        acc += h * h;
    }
#pragma unroll
    for (int o = 16; o; o >>= 1) acc += __shfl_xor_sync(0xffffffffu, acc, o);
    __shared__ float fs[8];
    if (lane == 0) fs[warp] = acc;
    __syncthreads();
    if (threadIdx.x == 0) {
        float t = 0.0f;
#pragma unroll
        for (int k = 0; k < 8; ++k) t += fs[k];
        atomicAdd(&g_sum, (double)t);
        __threadfence();
        if (atomicAdd(&g_done, 1) == (N_ / 8) - 1) {
            long long np = 0;
            for (int k = 0; k < 16; ++k) { long long nn = g_cnt[k]; np += nn * (nn - 1); }
            out[0] = (float)(g_sum / (2.0 * (double)np));
        }
    }
}

extern "C" void kernel_launch(void* const* d_in, const int* in_sizes, int n_in,
                              void* d_out, int out_size) {
    const float* a = (const float*)d_in[0];
    const float* b = (const float*)d_in[1];
    const int* labels = (const int*)d_in[2];
    float* out = (float*)d_out;

    cudaFuncSetAttribute(dist_kernel, cudaFuncAttributeMaxDynamicSharedMemorySize, SMEM_TOTAL);

    perm_kernel<<<1, 1024>>>(labels);
    prep_kernel<<<2 * N_, 128>>>(a, b);
    dim3 grid(N_ / TNJ, N_ / TM);
    dist_kernel<<<grid, 256, SMEM_TOTAL>>>();
    loss_kernel<<<N_ / 8, 256>>>(out);
}

// round 12
// speedup vs baseline: 1.2078x; 1.0235x over previous
#include <cuda_runtime.h>
#include <cuda_fp16.h>
#include <cstdint>
#include <math.h>

#define N_ 4096
#define F_ 512
#define TM 128
#define TNJ 128
#define BK 64
#define NCH (F_ / BK)            // 8 k-chunks
#define TILE_BYTES 16384         // 128 rows x 128B
#define STAGE_BYTES (2 * TILE_BYTES)   // 32KB
#define SMEM_TOTAL (3 * STAGE_BYTES)   // 98304, 2 CTAs/SM
#define PMAX 512                 // slots per row (max class size ~305)

// ---------------- scratch ----------------
__device__ __align__(16) __half g_ah[(size_t)N_ * F_];   // permuted rows
__device__ __align__(16) __half g_bh[(size_t)N_ * F_];   // permuted rows
__device__ float g_posD[(size_t)N_ * PMAX];   // D[perm_i][rank_j] for positives
__device__ float g_negsum[N_];                // permuted space
__device__ float g_a2[N_], g_b2[N_];          // permuted space
__device__ int   g_meta[N_];                  // (cls<<16)|rank per permuted index
__device__ int   g_permpos[N_];               // original row -> permuted position
__device__ int   g_cnt[16];
__device__ int   g_start[16];
__device__ double g_sum;
__device__ int   g_done;

// ---------------- helpers ----------------
__device__ __forceinline__ uint32_t smem_u32(const void* p) {
    uint32_t r;
    asm("{ .reg .u64 t; cvta.to.shared.u64 t, %1; cvt.u32.u64 %0, t; }" : "=r"(r) : "l"(p));
    return r;
}
__device__ __forceinline__ float fsqrt_ap(float x) {
    float r; asm("sqrt.approx.f32 %0, %1;" : "=f"(r) : "f"(x)); return r;
}

#define LDSM4(r, addr) \
    asm volatile("ldmatrix.sync.aligned.m8n8.x4.shared.b16 {%0,%1,%2,%3}, [%4];" \
                 : "=r"((r)[0]), "=r"((r)[1]), "=r"((r)[2]), "=r"((r)[3]) : "r"(addr))

// fp16-accumulator HMMA: D/C are 2 packed f16x2 regs
#define MMA16816H(d, a, b0, b1) \
    asm volatile("mma.sync.aligned.m16n8k16.row.col.f16.f16.f16.f16 " \
                 "{%0,%1}, {%2,%3,%4,%5}, {%6,%7}, {%0,%1};" \
                 : "+r"((d)[0]), "+r"((d)[1]) \
                 : "r"((a)[0]), "r"((a)[1]), "r"((a)[2]), "r"((a)[3]), "r"(b0), "r"(b1))

#define CP_ASYNC16(saddr, gptr) \
    asm volatile("cp.async.cg.shared.global [%0], [%1], 16;" :: "r"(saddr), "l"(gptr))
#define CP_COMMIT() asm volatile("cp.async.commit_group;" ::: "memory")
#define CP_WAIT1()  asm volatile("cp.async.wait_group 1;" ::: "memory")
#define CP_WAIT0()  asm volatile("cp.async.wait_group 0;" ::: "memory")

// ---------------- perm: class-sort permutation, meta, counts (1 block) ----------------
__global__ void perm_kernel(const int* __restrict__ labels) {
    __shared__ int sc[16], sstart[16];
    int tid = threadIdx.x;
    if (tid < 16) sc[tid] = 0;
    if (tid == 0) { g_sum = 0.0; g_done = 0; }
    __syncthreads();
    for (int e = tid; e < N_; e += blockDim.x) atomicAdd(&sc[labels[e]], 1);
    __syncthreads();
    if (tid == 0) {
        int acc = 0;
        for (int c = 0; c < 16; ++c) { sstart[c] = acc; g_start[c] = acc;
                                       g_cnt[c] = sc[c]; acc += sc[c]; }
    }
    __syncthreads();
    if (tid < 16) sc[tid] = 0;
    __syncthreads();
    for (int e = tid; e < N_; e += blockDim.x) {
        int c = labels[e];
        int r = atomicAdd(&sc[c], 1);
        int pos = sstart[c] + r;
        g_permpos[e] = pos;
        g_meta[pos] = (c << 16) | r;
    }
}

// ---------------- prep: 2 rows per 256-thr block (MLP=2) ----------------
// grid 4096: block q<2048 -> a rows 2q,2q+1 ; else b rows
__global__ __launch_bounds__(256)
void prep_kernel(const float* __restrict__ a, const float* __restrict__ b) {
    int q = blockIdx.x & 2047;
    bool isA = blockIdx.x < 2048;
    int r0 = q * 2, r1 = r0 + 1;
    const float* src = isA ? a : b;
    int tid = threadIdx.x;
    int lane = tid & 31, w = tid >> 5;

    float4 v0 = ((const float4*)(src + (size_t)r0 * F_))[tid >> 1];
    float4 v1 = ((const float4*)(src + (size_t)r1 * F_))[tid >> 1];
    // even threads handle row0 conversion slot, odd row1 (both loaded for MLP)
    // simpler: thread handles element (tid>>1) of row (tid&1)
    float4 v = (tid & 1) ? v1 : v0;
    int rr = (tid & 1) ? r1 : r0;
    int pos = g_permpos[rr];
    unsigned short h0 = __half_as_ushort(__float2half(v.x));
    unsigned short h1 = __half_as_ushort(__float2half(v.y));
    unsigned short h2 = __half_as_ushort(__float2half(v.z));
    unsigned short h3 = __half_as_ushort(__float2half(v.w));
    ((uint2*)(isA ? g_ah : g_bh))[pos * (F_ / 4) + (tid >> 1)] =
        make_uint2(((uint32_t)h1 << 16) | h0, ((uint32_t)h3 << 16) | h2);

    float s = v.x * v.x + v.y * v.y + v.z * v.z + v.w * v.w;
    // reduce separately over even (row0) and odd (row1) lanes:
#pragma unroll
    for (int o = 16; o >= 2; o >>= 1) s += __shfl_xor_sync(0xffffffffu, s, o);
    __shared__ float ws[16];
    if (lane < 2) ws[w * 2 + lane] = s;    // lane0 -> row0 partial, lane1 -> row1 partial
    __syncthreads();
    if (tid < 2) {
        float t = 0.0f;
#pragma unroll
        for (int k = 0; k < 8; ++k) t += ws[k * 2 + tid];
        int rr2 = tid ? r1 : r0;
        int p2 = g_permpos[rr2];
        if (isA) { g_a2[p2] = t; g_negsum[p2] = 0.0f; }
        else g_b2[p2] = t;
    }
}

// ---------------- dist kernel ----------------
__device__ __forceinline__ void load_stage(uint32_t sb, uint32_t koff,
                                           const char* baseB, const char* baseA,
                                           const uint32_t* goff, const uint32_t* smoff) {
#pragma unroll
    for (int k = 0; k < 4; ++k) CP_ASYNC16(sb + smoff[k], baseB + goff[k] + koff);
#pragma unroll
    for (int k = 4; k < 8; ++k) CP_ASYNC16(sb + smoff[k], baseA + goff[k] + koff);
}

__global__ __launch_bounds__(256, 2)
void dist_kernel() {
    extern __shared__ char smem[];
    const uint32_t sbase = smem_u32(smem);
    const int tid = threadIdx.x;
    const int wid = tid >> 5;
    const int lane = tid & 31;
    const int bi0 = blockIdx.y * TM;
    const int aj0 = blockIdx.x * TNJ;
    const int wm = (wid & 1) * 64;
    const int wn = (wid >> 1) * 32;

    uint32_t goff[8], smoff[8];
#pragma unroll
    for (int t = 0; t < 2; ++t)
#pragma unroll
        for (int q = 0; q < 4; ++q) {
            int linear = tid * 4 + q;
            int r = linear >> 3, cch = linear & 7;
            int row = (t ? aj0 : bi0) + r;
            goff[t * 4 + q] = (uint32_t)(row * (F_ * 2) + cch * 16);
            smoff[t * 4 + q] = (uint32_t)(t * TILE_BYTES + r * 128 + ((cch ^ (r & 7)) << 4));
        }
    const char* baseB = (const char*)g_bh;
    const char* baseA = (const char*)g_ah;

    uint32_t acc[4][4][2];
#pragma unroll
    for (int am = 0; am < 4; ++am)
#pragma unroll
        for (int an = 0; an < 4; ++an) { acc[am][an][0] = 0u; acc[am][an][1] = 0u; }

    load_stage(sbase, 0, baseB, baseA, goff, smoff);                 CP_COMMIT();
    load_stage(sbase + STAGE_BYTES, 128, baseB, baseA, goff, smoff); CP_COMMIT();

    const int lr = lane & 15;
    const int lh = lane >> 4;

#pragma unroll
    for (int c = 0; c < NCH; ++c) {
        if (c < NCH - 1) { CP_WAIT1(); } else { CP_WAIT0(); }
        __syncthreads();
        if (c + 2 < NCH) {
            load_stage(sbase + (uint32_t)((c + 2) % 3) * STAGE_BYTES,
                       (uint32_t)(c + 2) * 128, baseB, baseA, goff, smoff);
            CP_COMMIT();
        }
        uint32_t sb = sbase + (uint32_t)(c % 3) * STAGE_BYTES;

#pragma unroll
        for (int ks = 0; ks < 4; ++ks) {
            uint32_t abh[4][4], bah[2][4];
#pragma unroll
            for (int am = 0; am < 4; ++am) {
                int row = wm + am * 16 + lr;
                uint32_t off = (uint32_t)(row * 128) +
                               (((uint32_t)((ks * 2 + lh) ^ (row & 7))) << 4);
                LDSM4(abh[am], sb + off);
            }
#pragma unroll
            for (int np = 0; np < 2; ++np) {
                int row = wn + np * 16 + lr;
                uint32_t off = (uint32_t)(row * 128) +
                               (((uint32_t)((ks * 2 + lh) ^ (row & 7))) << 4);
                LDSM4(bah[np], sb + TILE_BYTES + off);
            }
#pragma unroll
            for (int am = 0; am < 4; ++am)
#pragma unroll
                for (int an = 0; an < 4; ++an) {
                    uint32_t h0 = bah[an >> 1][an & 1], h1 = bah[an >> 1][(an & 1) + 2];
                    MMA16816H(acc[am][an], abh[am], h0, h1);
                }
        }
    }

    // ------- epilogue: masked negsum + contiguous-window positive store -------
    const int lrow2 = lane >> 2;
    const int lcol = (lane & 3) * 2;
    const int colbase = aj0 + wn + lcol;

    float a2c[4][2];
    int cm[4][2];
#pragma unroll
    for (int an = 0; an < 4; ++an) {
        int gj = colbase + an * 8;
        a2c[an][0] = g_a2[gj];   a2c[an][1] = g_a2[gj + 1];
        cm[an][0] = g_meta[gj];  cm[an][1] = g_meta[gj + 1];
    }

#pragma unroll
    for (int am = 0; am < 4; ++am) {
        int r0 = bi0 + wm + am * 16 + lrow2;
        int r1 = r0 + 8;
        float b20 = g_b2[r0], b21 = g_b2[r1];
        int cl0 = g_meta[r0] >> 16, cl1 = g_meta[r1] >> 16;
        float* p0 = g_posD + (size_t)r0 * PMAX;
        float* p1 = g_posD + (size_t)r1 * PMAX;
        float n0 = 0.0f, n1 = 0.0f;
#pragma unroll
        for (int an = 0; an < 4; ++an) {
            __half2 h0 = *reinterpret_cast<__half2*>(&acc[am][an][0]);
            __half2 h1 = *reinterpret_cast<__half2*>(&acc[am][an][1]);
            float dot[2][2] = {{__low2float(h0), __high2float(h0)},
                               {__low2float(h1), __high2float(h1)}};
#pragma unroll
            for (int cc = 0; cc < 2; ++cc) {
                int gj = colbase + an * 8 + cc;
                int cls = cm[an][cc] >> 16, rnk = cm[an][cc] & 0xffff;
                float dd0 = fsqrt_ap(fmaxf(b20 + a2c[an][cc] - 2.0f * dot[0][cc], 0.0f));
                if (cls != cl0) n0 += __expf(1.0f - dd0);
                else if (gj != r0) p0[rnk] = dd0;
                float dd1 = fsqrt_ap(fmaxf(b21 + a2c[an][cc] - 2.0f * dot[1][cc], 0.0f));
                if (cls != cl1) n1 += __expf(1.0f - dd1);
                else if (gj != r1) p1[rnk] = dd1;
            }
        }
        n0 += __shfl_xor_sync(0xffffffffu, n0, 1);
        n0 += __shfl_xor_sync(0xffffffffu, n0, 2);
        n1 += __shfl_xor_sync(0xffffffffu, n1, 1);
        n1 += __shfl_xor_sync(0xffffffffu, n1, 2);
        if ((lane & 3) == 0) {
            atomicAdd(&g_negsum[r0], n0);
            atomicAdd(&g_negsum[r1], n1);
        }
    }
}

// ---------------- loss: 16 warps/block, warp per row, 2-way ILP; last block finalizes ----------------
__global__ __launch_bounds__(512)
void loss_kernel(float* __restrict__ out) {
    int lane = threadIdx.x & 31;
    int warp = threadIdx.x >> 5;
    int i = blockIdx.x * 16 + warp;
    int m = g_meta[i];
    int c = m >> 16, ri = m & 0xffff;
    int s = g_start[c], n = g_cnt[c];
    float nsi = g_negsum[i];
    const float* pD = g_posD + (size_t)i * PMAX;
    const float* ns = g_negsum + s;
    float acc = 0.0f;
    int t = lane;
    for (; t + 32 < n; t += 64) {
        float pa = pD[t], nsa = ns[t];
        float pb = pD[t + 32], nsb = ns[t + 32];
        if (t != ri) {
            float J = __logf(nsi + nsa) + pa;
            float h = fmaxf(J, 0.0f);
            acc += h * h;
        }
        if (t + 32 != ri) {
            float J = __logf(nsi + nsb) + pb;
            float h = fmaxf(J, 0.0f);
            acc += h * h;
        }
    }
    if (t < n && t != ri) {
        float J = __logf(nsi + ns[t]) + pD[t];
        float h = fmaxf(J, 0.0f);
        acc += h * h;
    }
#pragma unroll
    for (int o = 16; o; o >>= 1) acc += __shfl_xor_sync(0xffffffffu, acc, o);
    __shared__ float fs[16];
    if (lane == 0) fs[warp] = acc;
    __syncthreads();
    if (threadIdx.x == 0) {
        float tt = 0.0f;
#pragma unroll
        for (int k = 0; k < 16; ++k) tt += fs[k];
        atomicAdd(&g_sum, (double)tt);
        __threadfence();
        if (atomicAdd(&g_done, 1) == (N_ / 16) - 1) {
            long long np = 0;
            for (int k = 0; k < 16; ++k) { long long nn = g_cnt[k]; np += nn * (nn - 1); }
            out[0] = (float)(g_sum / (2.0 * (double)np));
        }
    }
}

extern "C" void kernel_launch(void* const* d_in, const int* in_sizes, int n_in,
                              void* d_out, int out_size) {
    const float* a = (const float*)d_in[0];
    const float* b = (const float*)d_in[1];
    const int* labels = (const int*)d_in[2];
    float* out = (float*)d_out;

    cudaFuncSetAttribute(dist_kernel, cudaFuncAttributeMaxDynamicSharedMemorySize, SMEM_TOTAL);

    perm_kernel<<<1, 1024>>>(labels);
    prep_kernel<<<4096, 256>>>(a, b);
    dim3 grid(N_ / TNJ, N_ / TM);
    dist_kernel<<<grid, 256, SMEM_TOTAL>>>();
    loss_kernel<<<N_ / 16, 512>>>(out);
}